// round 7
// baseline (speedup 1.0000x reference)
#include <cuda_runtime.h>

#define IN_DIM 256
#define FEAT   33152      // 256 + (256 + 256*256)/2 = 259 * 128
#define NB     8          // batch
#define NROWS  8192       // NHEAD * S * D_MODEL
#define NCHUNK 259        // FEAT / 128, exact
#define STAGES 6
#define OUTF   64

typedef unsigned long long u64;

// scratch (allocation-free rule: __device__ globals)
__device__ __align__(16) float g_feats[NB * FEAT];
__device__ __align__(16) float g_head[NB * NROWS];

// packed dual-FMA: d.lo = a.lo*b.lo + c.lo ; d.hi = a.hi*b.hi + c.hi
__device__ __forceinline__ u64 ffma2(u64 a, u64 b, u64 c) {
    u64 d;
    asm("fma.rn.f32x2 %0, %1, %2, %3;" : "=l"(d) : "l"(a), "l"(b), "l"(c));
    return d;
}

__device__ __forceinline__ float sum2(u64 v) {
    union { u64 u; float f[2]; } cvt;
    cvt.u = v;
    return cvt.f[0] + cvt.f[1];
}

// default-cached (L1-resident) 16B load for feats
__device__ __forceinline__ ulonglong2 ldca128(const void* p) {
    ulonglong2 v;
    asm("ld.global.ca.v2.u64 {%0, %1}, [%2];"
        : "=l"(v.x), "=l"(v.y) : "l"(p));
    return v;
}

// fire-and-forget 16B global->shared copy (bypasses L1, no register target)
__device__ __forceinline__ void cp_async16(void* smem_dst, const void* gsrc) {
    unsigned saddr = (unsigned)__cvta_generic_to_shared(smem_dst);
    asm volatile("cp.async.cg.shared.global [%0], [%1], 16;" :: "r"(saddr), "l"(gsrc));
}

// ---------------------------------------------------------------------------
// Kernel A: build feats = [x_flat | triu(x x^T)] for all 8 batches.
// ---------------------------------------------------------------------------
__global__ void build_feats_kernel(const float* __restrict__ x) {
    __shared__ float xs[NB][IN_DIM];
    int tid = threadIdx.x;                       // 256 threads
    for (int t = tid; t < NB * IN_DIM; t += 256)
        xs[t >> 8][t & 255] = x[t];
    __syncthreads();

    int i = blockIdx.x;
    if (i < IN_DIM) {
        int j = tid;
        if (j >= i) {
            int off = IN_DIM + i * IN_DIM - (i * (i - 1)) / 2 + (j - i);
            #pragma unroll
            for (int b = 0; b < NB; b++)
                g_feats[b * FEAT + off] = xs[b][i] * xs[b][j];
        }
    } else {
        int j = tid;
        #pragma unroll
        for (int b = 0; b < NB; b++)
            g_feats[b * FEAT + j] = xs[b][j];
    }
}

// ---------------------------------------------------------------------------
// Kernel B: head_out[b][r] = dot(feats[b], W[r]) + bh[r]
//   R4 shape (64 thr, 2 warps, 4 rows/warp, feats via L1 .ca) but W now
//   flows through a 6-stage cp.async smem pipeline: depth decoupled from
//   registers -> ~140 KB of W in flight per SM. grid=1024, 7 blocks/SM.
// ---------------------------------------------------------------------------
__global__ void __launch_bounds__(64, 7)
head_gemm_kernel(const float* __restrict__ W, const float* __restrict__ bh) {
    __shared__ __align__(16) float sw[STAGES][8][128];   // 24 KB

    int tid  = threadIdx.x;
    int warp = tid >> 5;                 // 0..1
    int lane = tid & 31;
    int row0 = blockIdx.x * 8;

    const float* wbase = W + (size_t)row0 * FEAT;
    const float* fb    = g_feats + lane * 4;

    // fill helper indices: tid covers 256 x 16B per stage, 4 per thread
    int frow[4], fseg[4];
    #pragma unroll
    for (int q = 0; q < 4; q++) {
        int idx = q * 64 + tid;
        frow[q] = idx >> 5;
        fseg[q] = (idx & 31) << 2;
    }

    u64 acc[4][8];
    #pragma unroll
    for (int r = 0; r < 4; r++)
        #pragma unroll
        for (int b = 0; b < 8; b++) acc[r][b] = 0ull;

    // ---- prologue: fill stages 0..4 ----
    #pragma unroll
    for (int s = 0; s < STAGES - 1; s++) {
        #pragma unroll
        for (int q = 0; q < 4; q++)
            cp_async16(&sw[s][frow[q]][fseg[q]],
                       wbase + (size_t)frow[q] * FEAT + s * 128 + fseg[q]);
        asm volatile("cp.async.commit_group;");
    }

    const float* srw = &sw[0][warp * 4][0];      // warp's 4 rows base (slot 0)

    #pragma unroll 1
    for (int it = 0; it < NCHUNK; it++) {
        asm volatile("cp.async.wait_group 4;");
        __syncthreads();

        // prefetch stage it+5 into slot (it+5)%6; always commit (may be empty)
        int pf = it + STAGES - 1;
        if (pf < NCHUNK) {
            int slot = pf % STAGES;
            #pragma unroll
            for (int q = 0; q < 4; q++)
                cp_async16(&sw[slot][frow[q]][fseg[q]],
                           wbase + (size_t)frow[q] * FEAT + pf * 128 + fseg[q]);
        }
        asm volatile("cp.async.commit_group;");

        int slot = it % STAGES;
        const float* wrow = &sw[slot][warp * 4][lane * 4];
        ulonglong2 a0 = *(const ulonglong2*)(wrow);
        ulonglong2 a1 = *(const ulonglong2*)(wrow + 128);
        ulonglong2 a2 = *(const ulonglong2*)(wrow + 256);
        ulonglong2 a3 = *(const ulonglong2*)(wrow + 384);

        const float* fk = fb + it * 128;
        #pragma unroll
        for (int b = 0; b < 8; b++) {
            ulonglong2 f = ldca128(fk + b * FEAT);
            acc[0][b] = ffma2(a0.x, f.x, acc[0][b]);
            acc[0][b] = ffma2(a0.y, f.y, acc[0][b]);
            acc[1][b] = ffma2(a1.x, f.x, acc[1][b]);
            acc[1][b] = ffma2(a1.y, f.y, acc[1][b]);
            acc[2][b] = ffma2(a2.x, f.x, acc[2][b]);
            acc[2][b] = ffma2(a2.y, f.y, acc[2][b]);
            acc[3][b] = ffma2(a3.x, f.x, acc[3][b]);
            acc[3][b] = ffma2(a3.y, f.y, acc[3][b]);
        }
    }

    int rbase = warp * 4;
    #pragma unroll
    for (int r = 0; r < 4; r++) {
        #pragma unroll
        for (int b = 0; b < 8; b++) {
            float v = sum2(acc[r][b]);
            #pragma unroll
            for (int o = 16; o > 0; o >>= 1)
                v += __shfl_xor_sync(0xffffffffu, v, o);
            if (lane == 0)
                g_head[b * NROWS + row0 + rbase + r] = v + bh[row0 + rbase + r];
        }
    }
}

// ---------------------------------------------------------------------------
// Kernel C: out[b][s][o] = dot(concat[b][s], W_out[o]) + b_out[o]
// ---------------------------------------------------------------------------
__global__ void out_gemm_kernel(const float* __restrict__ Wout,
                                const float* __restrict__ bout,
                                float* __restrict__ out) {
    __shared__ float cs[256];
    int bs = blockIdx.x;
    int b  = bs >> 5;
    int s  = bs & 31;
    int t  = threadIdx.x;    // 64 threads

    #pragma unroll
    for (int q = 0; q < 4; q++) {
        int j = t + q * 64;
        cs[j] = g_head[b * NROWS + (j >> 6) * 2048 + s * 64 + (j & 63)];
    }
    __syncthreads();

    const float* wr = Wout + t * 256;
    float sum = bout[t];
    #pragma unroll
    for (int j = 0; j < 256; j += 4) {
        float4 w = *(const float4*)(wr + j);
        sum = fmaf(w.x, cs[j],
              fmaf(w.y, cs[j + 1],
              fmaf(w.z, cs[j + 2],
              fmaf(w.w, cs[j + 3], sum))));
    }
    out[bs * 64 + t] = sum;
}

// ---------------------------------------------------------------------------
extern "C" void kernel_launch(void* const* d_in, const int* in_sizes, int n_in,
                              void* d_out, int out_size) {
    const float* x   = (const float*)d_in[0];   // (8,32,8)
    const float* W   = (const float*)d_in[1];   // (4,2048,33152)
    const float* bh  = (const float*)d_in[2];   // (4,2048)
    const float* Wo  = (const float*)d_in[3];   // (64,256)
    const float* bo  = (const float*)d_in[4];   // (64,)
    float* out = (float*)d_out;                 // (8,32,64)

    build_feats_kernel<<<IN_DIM + 1, 256>>>(x);
    head_gemm_kernel<<<NROWS / 8, 64>>>(W, bh);
    out_gemm_kernel<<<256, 64>>>(Wo, bo, out);
}

// round 8
// speedup vs baseline: 1.3672x; 1.3672x over previous
#include <cuda_runtime.h>

#define IN_DIM 256
#define FEAT   33152      // 256 + (256 + 256*256)/2 = 259 * 128
#define NB     8          // batch
#define NROWS  8192       // NHEAD * S * D_MODEL
#define NCHUNK 259        // FEAT / 128, exact
#define STAGES 5
#define OUTF   64

typedef unsigned long long u64;

// scratch (allocation-free rule: __device__ globals)
__device__ __align__(16) float g_feats[NB * FEAT];
__device__ __align__(16) float g_head[NB * NROWS];

// packed dual-FMA: d.lo = a.lo*b.lo + c.lo ; d.hi = a.hi*b.hi + c.hi
__device__ __forceinline__ u64 ffma2(u64 a, u64 b, u64 c) {
    u64 d;
    asm("fma.rn.f32x2 %0, %1, %2, %3;" : "=l"(d) : "l"(a), "l"(b), "l"(c));
    return d;
}

__device__ __forceinline__ float sum2(u64 v) {
    union { u64 u; float f[2]; } cvt;
    cvt.u = v;
    return cvt.f[0] + cvt.f[1];
}

// default-cached (L1-resident) 16B load for feats
__device__ __forceinline__ ulonglong2 ldca128(const void* p) {
    ulonglong2 v;
    asm("ld.global.ca.v2.u64 {%0, %1}, [%2];"
        : "=l"(v.x), "=l"(v.y) : "l"(p));
    return v;
}

__device__ __forceinline__ unsigned smem_u32(const void* p) {
    return (unsigned)__cvta_generic_to_shared(p);
}

// bulk async copy global->shared::cta, completion counted on mbarrier
__device__ __forceinline__ void bulk_cp(unsigned dst, const void* src,
                                        unsigned bytes, unsigned mbar) {
    asm volatile(
        "cp.async.bulk.shared::cta.global.mbarrier::complete_tx::bytes "
        "[%0], [%1], %2, [%3];"
        :: "r"(dst), "l"(src), "r"(bytes), "r"(mbar) : "memory");
}

// ---------------------------------------------------------------------------
// Kernel A: build feats = [x_flat | triu(x x^T)] for all 8 batches.
// ---------------------------------------------------------------------------
__global__ void build_feats_kernel(const float* __restrict__ x) {
    __shared__ float xs[NB][IN_DIM];
    int tid = threadIdx.x;                       // 256 threads
    for (int t = tid; t < NB * IN_DIM; t += 256)
        xs[t >> 8][t & 255] = x[t];
    __syncthreads();

    int i = blockIdx.x;
    if (i < IN_DIM) {
        int j = tid;
        if (j >= i) {
            int off = IN_DIM + i * IN_DIM - (i * (i - 1)) / 2 + (j - i);
            #pragma unroll
            for (int b = 0; b < NB; b++)
                g_feats[b * FEAT + off] = xs[b][i] * xs[b][j];
        }
    } else {
        int j = tid;
        #pragma unroll
        for (int b = 0; b < NB; b++)
            g_feats[b * FEAT + j] = xs[b][j];
    }
}

// ---------------------------------------------------------------------------
// Kernel B: head_out[b][r] = dot(feats[b], W[r]) + bh[r]
//   R4 shape (1024 blocks x 64 thr, 4 rows/warp, feats via L1 .ca) with W
//   routed through a 5-stage cp.async.bulk (TMA-engine) smem ring: in-flight
//   W bytes decoupled from registers AND from LDG tag limits (~112 KB/SM).
// ---------------------------------------------------------------------------
__global__ void __launch_bounds__(64, 7)
head_gemm_kernel(const float* __restrict__ W, const float* __restrict__ bh) {
    __shared__ __align__(16) float sw[STAGES][8][128];   // 20 KB
    __shared__ __align__(8)  u64  mbar[STAGES];

    int tid  = threadIdx.x;
    int warp = tid >> 5;                 // 0..1
    int lane = tid & 31;
    int row0 = blockIdx.x * 8;

    const float* wbase = W + (size_t)row0 * FEAT;
    const float* fk    = g_feats + lane * 4;   // advances 128 floats/iter

    unsigned baru[STAGES];
    #pragma unroll
    for (int s = 0; s < STAGES; s++) baru[s] = smem_u32(&mbar[s]);

    if (tid == 0) {
        #pragma unroll
        for (int s = 0; s < STAGES; s++)
            asm volatile("mbarrier.init.shared.b64 [%0], 1;" :: "r"(baru[s]) : "memory");
    }
    __syncthreads();

    // prologue: stages 0..4 <- chunks 0..4
    if (tid == 0) {
        #pragma unroll
        for (int s = 0; s < STAGES; s++) {
            asm volatile("mbarrier.arrive.expect_tx.shared.b64 _, [%0], %1;"
                         :: "r"(baru[s]), "r"(4096u) : "memory");
            #pragma unroll
            for (int r = 0; r < 8; r++)
                bulk_cp(smem_u32(&sw[s][r][0]),
                        wbase + (size_t)r * FEAT + s * 128, 512, baru[s]);
        }
    }

    u64 acc[4][8];
    #pragma unroll
    for (int r = 0; r < 4; r++)
        #pragma unroll
        for (int b = 0; b < 8; b++) acc[r][b] = 0ull;

    int slot = 0, ph = 0;

    #pragma unroll 1
    for (int it = 0; it < NCHUNK; it++) {
        // wait chunk ready (acquire)
        {
            unsigned done = 0;
            while (!done)
                asm volatile(
                    "{\n\t.reg .pred p;\n\t"
                    "mbarrier.try_wait.parity.acquire.cta.shared::cta.b64 p, [%1], %2, 0x989680;\n\t"
                    "selp.b32 %0, 1, 0, p;\n\t}"
                    : "=r"(done) : "r"(baru[slot]), "r"((unsigned)ph) : "memory");
        }

        const float* wrow = &sw[slot][warp * 4][lane * 4];
        ulonglong2 a0 = *(const ulonglong2*)(wrow);
        ulonglong2 a1 = *(const ulonglong2*)(wrow + 128);
        ulonglong2 a2 = *(const ulonglong2*)(wrow + 256);
        ulonglong2 a3 = *(const ulonglong2*)(wrow + 384);

        #pragma unroll
        for (int b = 0; b < 8; b++) {
            ulonglong2 f = ldca128(fk + b * FEAT);
            acc[0][b] = ffma2(a0.x, f.x, acc[0][b]);
            acc[0][b] = ffma2(a0.y, f.y, acc[0][b]);
            acc[1][b] = ffma2(a1.x, f.x, acc[1][b]);
            acc[1][b] = ffma2(a1.y, f.y, acc[1][b]);
            acc[2][b] = ffma2(a2.x, f.x, acc[2][b]);
            acc[2][b] = ffma2(a2.y, f.y, acc[2][b]);
            acc[3][b] = ffma2(a3.x, f.x, acc[3][b]);
            acc[3][b] = ffma2(a3.y, f.y, acc[3][b]);
        }
        fk += 128;

        __syncthreads();   // all warps consumed this slot (regs hold W via FFMA dep)

        int pf = it + STAGES;
        if (pf < NCHUNK && tid == 0) {
            asm volatile("mbarrier.arrive.expect_tx.shared.b64 _, [%0], %1;"
                         :: "r"(baru[slot]), "r"(4096u) : "memory");
            #pragma unroll
            for (int r = 0; r < 8; r++)
                bulk_cp(smem_u32(&sw[slot][r][0]),
                        wbase + (size_t)r * FEAT + (size_t)pf * 128, 512, baru[slot]);
        }

        if (++slot == STAGES) { slot = 0; ph ^= 1; }
    }

    int rbase = warp * 4;
    #pragma unroll
    for (int r = 0; r < 4; r++) {
        #pragma unroll
        for (int b = 0; b < 8; b++) {
            float v = sum2(acc[r][b]);
            #pragma unroll
            for (int o = 16; o > 0; o >>= 1)
                v += __shfl_xor_sync(0xffffffffu, v, o);
            if (lane == 0)
                g_head[b * NROWS + row0 + rbase + r] = v + bh[row0 + rbase + r];
        }
    }
}

// ---------------------------------------------------------------------------
// Kernel C: out[b][s][o] = dot(concat[b][s], W_out[o]) + b_out[o]
// ---------------------------------------------------------------------------
__global__ void out_gemm_kernel(const float* __restrict__ Wout,
                                const float* __restrict__ bout,
                                float* __restrict__ out) {
    __shared__ float cs[256];
    int bs = blockIdx.x;
    int b  = bs >> 5;
    int s  = bs & 31;
    int t  = threadIdx.x;    // 64 threads

    #pragma unroll
    for (int q = 0; q < 4; q++) {
        int j = t + q * 64;
        cs[j] = g_head[b * NROWS + (j >> 6) * 2048 + s * 64 + (j & 63)];
    }
    __syncthreads();

    const float* wr = Wout + t * 256;
    float sum = bout[t];
    #pragma unroll
    for (int j = 0; j < 256; j += 4) {
        float4 w = *(const float4*)(wr + j);
        sum = fmaf(w.x, cs[j],
              fmaf(w.y, cs[j + 1],
              fmaf(w.z, cs[j + 2],
              fmaf(w.w, cs[j + 3], sum))));
    }
    out[bs * 64 + t] = sum;
}

// ---------------------------------------------------------------------------
extern "C" void kernel_launch(void* const* d_in, const int* in_sizes, int n_in,
                              void* d_out, int out_size) {
    const float* x   = (const float*)d_in[0];   // (8,32,8)
    const float* W   = (const float*)d_in[1];   // (4,2048,33152)
    const float* bh  = (const float*)d_in[2];   // (4,2048)
    const float* Wo  = (const float*)d_in[3];   // (64,256)
    const float* bo  = (const float*)d_in[4];   // (64,)
    float* out = (float*)d_out;                 // (8,32,64)

    build_feats_kernel<<<IN_DIM + 1, 256>>>(x);
    head_gemm_kernel<<<NROWS / 8, 64>>>(W, bh);
    out_gemm_kernel<<<256, 64>>>(Wo, bo, out);
}